// round 6
// baseline (speedup 1.0000x reference)
#include <cuda_runtime.h>
#include <cuda_bf16.h>

#define B    128
#define N1   32
#define N2   32
#define D1   23
#define D2   13
#define NN   64
#define E    72
#define H    256
#define F    128
#define LNCNT 4608

typedef unsigned long long u64;

// ---- f32x2 packed helpers (sm_103a) ----
__device__ __forceinline__ u64 pk(float lo, float hi) {
    u64 r; asm("mov.b64 %0, {%1,%2};" : "=l"(r) : "f"(lo), "f"(hi)); return r;
}
__device__ __forceinline__ void upk(u64 x, float& lo, float& hi) {
    asm("mov.b64 {%0,%1}, %2;" : "=f"(lo), "=f"(hi) : "l"(x));
}
__device__ __forceinline__ u64 add2(u64 a, u64 b) {
    u64 d; asm("add.rn.f32x2 %0,%1,%2;" : "=l"(d) : "l"(a), "l"(b)); return d;
}
__device__ __forceinline__ u64 mul2(u64 a, u64 b) {
    u64 d; asm("mul.rn.f32x2 %0,%1,%2;" : "=l"(d) : "l"(a), "l"(b)); return d;
}
__device__ __forceinline__ u64 fma2(u64 a, u64 b, u64 c) {
    u64 d; asm("fma.rn.f32x2 %0,%1,%2,%3;" : "=l"(d) : "l"(a), "l"(b), "l"(c)); return d;
}
__device__ __forceinline__ float ex2f(float x) {
    float r; asm("ex2.approx.ftz.f32 %0, %1;" : "=f"(r) : "f"(x)); return r;
}
__device__ __forceinline__ u64 shfl_xor_u64(u64 x, int o) {
    float lo, hi; upk(x, lo, hi);
    lo = __shfl_xor_sync(~0u, lo, o);
    hi = __shfl_xor_sync(~0u, hi, o);
    return pk(lo, hi);
}

// ELU via precomputed exps: e = min(max(u+v,0), eu*ev - 1). No MUFU.
__device__ __forceinline__ u64 elu2x(u64 u2, u64 v2, u64 eu2, u64 ev2, u64 neg1) {
    u64 e;
    asm("{\n\t"
        ".reg .b64 t2, p2, em2;\n\t"
        ".reg .f32 t0, t1, m0, m1, r0, r1;\n\t"
        "add.rn.f32x2 t2, %1, %2;\n\t"
        "mul.rn.f32x2 p2, %3, %4;\n\t"
        "add.rn.f32x2 em2, p2, %5;\n\t"
        "mov.b64 {t0,t1}, t2;\n\t"
        "mov.b64 {m0,m1}, em2;\n\t"
        "max.f32 r0, t0, 0f00000000;\n\t"
        "max.f32 r1, t1, 0f00000000;\n\t"
        "min.f32 r0, r0, m0;\n\t"
        "min.f32 r1, r1, m1;\n\t"
        "mov.b64 %0, {r0,r1};\n\t"
        "}" : "=l"(e) : "l"(u2), "l"(v2), "l"(eu2), "l"(ev2), "l"(neg1));
    return e;
}

// Scratch
__device__ float g_a [B * NN * E];
__device__ float g_u [B * NN * H];
__device__ float g_v [B * NN * H];
__device__ float g_eu[B * NN * H];
__device__ float g_ev[B * NN * H];
__device__ float g_p [B * 16 * H];

// ---------------------------------------------------------------------------
// K1: split-embedding + joint LayerNorm over (N,E). One block per b.
// ---------------------------------------------------------------------------
__global__ __launch_bounds__(256) void k_embed_ln(
    const float* __restrict__ xa, const float* __restrict__ xb,
    const float* __restrict__ Wa, const float* __restrict__ ba,
    const float* __restrict__ Wb, const float* __restrict__ bb,
    const float* __restrict__ g0, const float* __restrict__ b0)
{
    const int b   = blockIdx.x;
    const int tid = threadIdx.x;
    __shared__ float rsum[8], rssq[8];
    __shared__ float s_mean, s_rstd;

    float vals[18];
    float sum = 0.f, ssq = 0.f;

    #pragma unroll
    for (int c = 0; c < 18; ++c) {
        const int idx = tid + c * 256;
        const int n = idx / E;
        const int e = idx - n * E;
        float acc;
        if (n < N1) {
            acc = ba[e];
            const float* xr = xa + (b * N1 + n) * D1;
            #pragma unroll
            for (int k = 0; k < D1; ++k) acc = fmaf(xr[k], Wa[k * E + e], acc);
        } else {
            acc = bb[e];
            const float* xr = xb + (b * N2 + (n - N1)) * D2;
            #pragma unroll
            for (int k = 0; k < D2; ++k) acc = fmaf(xr[k], Wb[k * E + e], acc);
        }
        vals[c] = acc;
        sum += acc;
        ssq = fmaf(acc, acc, ssq);
    }

    #pragma unroll
    for (int o = 16; o; o >>= 1) {
        sum += __shfl_xor_sync(~0u, sum, o);
        ssq += __shfl_xor_sync(~0u, ssq, o);
    }
    const int w = tid >> 5, lane = tid & 31;
    if (lane == 0) { rsum[w] = sum; rssq[w] = ssq; }
    __syncthreads();
    if (tid == 0) {
        float s = 0.f, q = 0.f;
        #pragma unroll
        for (int i = 0; i < 8; ++i) { s += rsum[i]; q += rssq[i]; }
        const float mean = s * (1.f / LNCNT);
        const float var  = fmaf(q, 1.f / LNCNT, -mean * mean);
        s_mean = mean;
        s_rstd = rsqrtf(var + 1e-5f);
    }
    __syncthreads();
    const float mean = s_mean, rstd = s_rstd;

    #pragma unroll
    for (int c = 0; c < 18; ++c) {
        const int idx = tid + c * 256;
        g_a[b * LNCNT + idx] = (vals[c] - mean) * rstd * g0[idx] + b0[idx];
    }
}

// ---------------------------------------------------------------------------
// K2: u = a @ Wg[0:72] + b_g ; v = a @ Wg[72:144]; also eu = e^u, ev = e^v.
// 16 rows/block, f32x2. grid = 512.
// ---------------------------------------------------------------------------
__global__ __launch_bounds__(256) void k_uv(
    const float* __restrict__ Wg, const float* __restrict__ bg)
{
    __shared__ float sa[E * 16];
    const int m0 = blockIdx.x * 16;
    const int h  = threadIdx.x;

    for (int idx = h; idx < E * 16; idx += 256) {
        const int rr = idx / E, k = idx - rr * E;
        sa[k * 16 + rr] = g_a[(m0 + rr) * E + k];
    }
    __syncthreads();

    const float bgh = bg[h];
    u64 uacc[8], vacc[8];
    const u64 bg2 = pk(bgh, bgh);
    #pragma unroll
    for (int p = 0; p < 8; ++p) { uacc[p] = bg2; vacc[p] = 0ull; }

    #pragma unroll 4
    for (int k = 0; k < E; ++k) {
        const ulonglong2* ar = (const ulonglong2*)&sa[k * 16];
        const ulonglong2 q0 = ar[0], q1 = ar[1], q2 = ar[2], q3 = ar[3];
        const u64 av[8] = {q0.x, q0.y, q1.x, q1.y, q2.x, q2.y, q3.x, q3.y};
        const float w0 = Wg[k * H + h];
        const float w1 = Wg[(E + k) * H + h];
        const u64 w02 = pk(w0, w0);
        const u64 w12 = pk(w1, w1);
        #pragma unroll
        for (int p = 0; p < 8; ++p) {
            uacc[p] = fma2(av[p], w02, uacc[p]);
            vacc[p] = fma2(av[p], w12, vacc[p]);
        }
    }

    const float L2E = 1.44269504f;
    #pragma unroll
    for (int p = 0; p < 8; ++p) {
        float lo, hi;
        upk(uacc[p], lo, hi);
        g_u [(m0 + 2 * p) * H + h]     = lo;
        g_u [(m0 + 2 * p + 1) * H + h] = hi;
        g_eu[(m0 + 2 * p) * H + h]     = ex2f(lo * L2E);
        g_eu[(m0 + 2 * p + 1) * H + h] = ex2f(hi * L2E);
        upk(vacc[p], lo, hi);
        g_v [(m0 + 2 * p) * H + h]     = lo;
        g_v [(m0 + 2 * p + 1) * H + h] = hi;
        g_ev[(m0 + 2 * p) * H + h]     = ex2f(lo * L2E);
        g_ev[(m0 + 2 * p + 1) * H + h] = ex2f(hi * L2E);
    }
}

// ---------------------------------------------------------------------------
// K3: pairwise Σ_j LN_H(ELU(u_i + v_j)), j split in halves per block.
// Block = (b, ig, jh): 8 warps = 8 i's, j in [jh*32, jh*32+32).
// Half-warp j-split (lanes 0-15 even local j, 16-31 odd; 16 ch/lane).
// smem: swizzled v-half (32KB) + ev-half (32KB). No MUFU in hot loop.
// ---------------------------------------------------------------------------
__global__ __launch_bounds__(256, 3) void k_pair(
    const float* __restrict__ lg, const float* __restrict__ lb)
{
    extern __shared__ float sm[];               // [2][32][256]
    float* svv = sm;
    float* sev = sm + 32 * H;

    const int bid  = blockIdx.x;
    const int b    = bid >> 4;
    const int ig   = (bid >> 1) & 7;
    const int jh   = bid & 1;
    const int tid  = threadIdx.x;
    const int w    = tid >> 5;
    const int lane = tid & 31;
    const int half = lane >> 4;
    const int sub  = lane & 15;
    const int ch0  = sub * 16;

    // stage v/ev halves with granule swizzle: float4 q of local row j ->
    // base4[j*64 + (q&3)*16 + (q>>2)]
    {
        const float4* vb = (const float4*)(g_v  + (b * NN + jh * 32) * H);
        const float4* eb = (const float4*)(g_ev + (b * NN + jh * 32) * H);
        float4* s4v = (float4*)svv;
        float4* s4e = (float4*)sev;
        #pragma unroll
        for (int c = 0; c < 8; ++c) {
            const int g = tid + c * 256;        // < 2048
            const int j = g >> 6;
            const int q = g & 63;
            const int off = j * 64 + (q & 3) * 16 + (q >> 2);
            s4v[off] = vb[g];
            s4e[off] = eb[g];
        }
    }

    const int m = b * NN + ig * 8 + w;

    u64 ru2[8], re2[8];
    {
        const ulonglong2* uu = (const ulonglong2*)(g_u + m * H + ch0);
        const ulonglong2 a0 = uu[0], a1 = uu[1], a2 = uu[2], a3 = uu[3];
        ru2[0] = a0.x; ru2[1] = a0.y; ru2[2] = a1.x; ru2[3] = a1.y;
        ru2[4] = a2.x; ru2[5] = a2.y; ru2[6] = a3.x; ru2[7] = a3.y;
        const ulonglong2* ee = (const ulonglong2*)(g_eu + m * H + ch0);
        const ulonglong2 b0 = ee[0], b1 = ee[1], b2 = ee[2], b3 = ee[3];
        re2[0] = b0.x; re2[1] = b0.y; re2[2] = b1.x; re2[3] = b1.y;
        re2[4] = b2.x; re2[5] = b2.y; re2[6] = b3.x; re2[7] = b3.y;
    }
    u64 acc2[8];
    const u64 NEG1 = pk(-1.f, -1.f);
    #pragma unroll
    for (int p = 0; p < 8; ++p) acc2[p] = 0ull;
    float smA = 0.f;

    __syncthreads();

    #pragma unroll 4
    for (int s = 0; s < 16; ++s) {
        const int jl = 2 * s + half;            // local row 0..31
        const ulonglong2* vr = (const ulonglong2*)(svv + jl * H);
        const ulonglong2* er = (const ulonglong2*)(sev + jl * H);

        u64 e2[8];
        {
            const ulonglong2 v0 = vr[sub],      e0 = er[sub];
            const ulonglong2 v1 = vr[16 + sub], e1 = er[16 + sub];
            const ulonglong2 v2 = vr[32 + sub], e2q = er[32 + sub];
            const ulonglong2 v3 = vr[48 + sub], e3 = er[48 + sub];
            e2[0] = elu2x(ru2[0], v0.x, re2[0], e0.x, NEG1);
            e2[1] = elu2x(ru2[1], v0.y, re2[1], e0.y, NEG1);
            e2[2] = elu2x(ru2[2], v1.x, re2[2], e1.x, NEG1);
            e2[3] = elu2x(ru2[3], v1.y, re2[3], e1.y, NEG1);
            e2[4] = elu2x(ru2[4], v2.x, re2[4], e2q.x, NEG1);
            e2[5] = elu2x(ru2[5], v2.y, re2[5], e2q.y, NEG1);
            e2[6] = elu2x(ru2[6], v3.x, re2[6], e3.x, NEG1);
            e2[7] = elu2x(ru2[7], v3.y, re2[7], e3.y, NEG1);
        }

        u64 se = add2(add2(add2(e2[0], e2[1]), add2(e2[2], e2[3])),
                      add2(add2(e2[4], e2[5]), add2(e2[6], e2[7])));
        u64 sq = mul2(e2[0], e2[0]);
        sq = fma2(e2[1], e2[1], sq); sq = fma2(e2[2], e2[2], sq);
        sq = fma2(e2[3], e2[3], sq); sq = fma2(e2[4], e2[4], sq);
        sq = fma2(e2[5], e2[5], sq); sq = fma2(e2[6], e2[6], sq);
        sq = fma2(e2[7], e2[7], sq);
        float selo, sehi, sqlo, sqhi;
        upk(se, selo, sehi); upk(sq, sqlo, sqhi);
        float sum = selo + sehi;
        float ssq = sqlo + sqhi;

        // butterfly within 16-lane half
        #pragma unroll
        for (int o = 8; o; o >>= 1) {
            sum += __shfl_xor_sync(~0u, sum, o);
            ssq += __shfl_xor_sync(~0u, ssq, o);
        }
        const float mean = sum * (1.f / H);
        const float var  = fmaf(ssq, 1.f / H, -mean * mean);
        const float A    = rsqrtf(var + 1e-5f);
        smA = fmaf(mean, A, smA);
        const u64 A2 = pk(A, A);
        #pragma unroll
        for (int p = 0; p < 8; ++p) acc2[p] = fma2(e2[p], A2, acc2[p]);
    }

    // merge even/odd-j halves
    #pragma unroll
    for (int p = 0; p < 8; ++p) acc2[p] = add2(acc2[p], shfl_xor_u64(acc2[p], 16));
    smA += __shfl_xor_sync(~0u, smA, 16);

    __syncthreads();                       // all warps done reading smem
    if (half == 0) {
        const u64 nsmA = pk(-smA, -smA);
        u64* dst = (u64*)&svv[w * H + ch0];
        #pragma unroll
        for (int p = 0; p < 8; ++p) dst[p] = add2(acc2[p], nsmA);
    }
    __syncthreads();
    {
        float s = 0.f;
        #pragma unroll
        for (int ww = 0; ww < 8; ++ww) s += svv[ww * H + tid];
        // this block covers 8 i * 32 j = 256 (i,j) pairs -> 256 * beta
        g_p[bid * H + tid] = fmaf(lg[tid], s, 256.f * lb[tid]);
    }
}

// ---------------------------------------------------------------------------
// K4: s[b] = Σ 16 partials; out = ELU(s @ W_f + b_f).
// 4-way F-split: 512 blocks, 256 thr.
// ---------------------------------------------------------------------------
__global__ __launch_bounds__(256) void k_final(
    const float* __restrict__ Wf, const float* __restrict__ bf,
    float* __restrict__ out)
{
    const int bid  = blockIdx.x;
    const int b    = bid >> 2;
    const int fq   = bid & 3;
    const int tid  = threadIdx.x;
    const int w    = tid >> 5;
    const int lane = tid & 31;
    __shared__ float ss[H];
    __shared__ float part[8][32];

    {
        float s = 0.f;
        #pragma unroll
        for (int ig = 0; ig < 16; ++ig) s += g_p[(b * 16 + ig) * H + tid];
        ss[tid] = s;
    }
    __syncthreads();

    const int f  = fq * 32 + lane;
    const int h0 = w * 32;
    float a0 = 0.f, a1 = 0.f, a2 = 0.f, a3 = 0.f;
    #pragma unroll
    for (int hh = 0; hh < 32; hh += 4) {
        a0 = fmaf(ss[h0 + hh + 0], Wf[(h0 + hh + 0) * F + f], a0);
        a1 = fmaf(ss[h0 + hh + 1], Wf[(h0 + hh + 1) * F + f], a1);
        a2 = fmaf(ss[h0 + hh + 2], Wf[(h0 + hh + 2) * F + f], a2);
        a3 = fmaf(ss[h0 + hh + 3], Wf[(h0 + hh + 3) * F + f], a3);
    }
    part[w][lane] = (a0 + a1) + (a2 + a3);
    __syncthreads();

    if (w == 0) {
        float o = bf[f];
        #pragma unroll
        for (int k = 0; k < 8; ++k) o += part[k][lane];
        out[b * F + f] = (o > 0.f) ? o : expm1f(o);
    }
}

// ---------------------------------------------------------------------------
extern "C" void kernel_launch(void* const* d_in, const int* in_sizes, int n_in,
                              void* d_out, int out_size)
{
    const float* x_a   = (const float*)d_in[0];
    const float* x_b   = (const float*)d_in[1];
    const float* W_a   = (const float*)d_in[2];
    const float* b_a   = (const float*)d_in[3];
    const float* W_b   = (const float*)d_in[4];
    const float* b_b   = (const float*)d_in[5];
    const float* ln0_g = (const float*)d_in[6];
    const float* ln0_b = (const float*)d_in[7];
    const float* W_g   = (const float*)d_in[8];
    const float* b_g   = (const float*)d_in[9];
    const float* lng_g = (const float*)d_in[10];
    const float* lng_b = (const float*)d_in[11];
    const float* W_f   = (const float*)d_in[12];
    const float* b_f   = (const float*)d_in[13];
    float* out = (float*)d_out;

    k_embed_ln<<<B, 256>>>(x_a, x_b, W_a, b_a, W_b, b_b, ln0_g, ln0_b);
    k_uv<<<B * NN / 16, 256>>>(W_g, b_g);

    const size_t smem = 2 * 32 * H * sizeof(float);   // 64 KB
    cudaFuncSetAttribute(k_pair, cudaFuncAttributeMaxDynamicSharedMemorySize, (int)smem);
    k_pair<<<B * 16, 256, smem>>>(lng_g, lng_b);

    k_final<<<B * 4, 256>>>(W_f, b_f, out);
}

// round 7
// speedup vs baseline: 1.0277x; 1.0277x over previous
#include <cuda_runtime.h>
#include <cuda_bf16.h>

#define B    128
#define N1   32
#define N2   32
#define D1   23
#define D2   13
#define NN   64
#define E    72
#define H    256
#define F    128
#define LNCNT 4608

typedef unsigned long long u64;

// ---- f32x2 packed helpers (sm_103a) ----
__device__ __forceinline__ u64 pk(float lo, float hi) {
    u64 r; asm("mov.b64 %0, {%1,%2};" : "=l"(r) : "f"(lo), "f"(hi)); return r;
}
__device__ __forceinline__ void upk(u64 x, float& lo, float& hi) {
    asm("mov.b64 {%0,%1}, %2;" : "=f"(lo), "=f"(hi) : "l"(x));
}
__device__ __forceinline__ u64 add2(u64 a, u64 b) {
    u64 d; asm("add.rn.f32x2 %0,%1,%2;" : "=l"(d) : "l"(a), "l"(b)); return d;
}
__device__ __forceinline__ u64 mul2(u64 a, u64 b) {
    u64 d; asm("mul.rn.f32x2 %0,%1,%2;" : "=l"(d) : "l"(a), "l"(b)); return d;
}
__device__ __forceinline__ u64 fma2(u64 a, u64 b, u64 c) {
    u64 d; asm("fma.rn.f32x2 %0,%1,%2,%3;" : "=l"(d) : "l"(a), "l"(b), "l"(c)); return d;
}
__device__ __forceinline__ float ex2f(float x) {
    float r; asm("ex2.approx.ftz.f32 %0, %1;" : "=f"(r) : "f"(x)); return r;
}
__device__ __forceinline__ u64 shfl_xor_u64(u64 x, int o) {
    float lo, hi; upk(x, lo, hi);
    lo = __shfl_xor_sync(~0u, lo, o);
    hi = __shfl_xor_sync(~0u, hi, o);
    return pk(lo, hi);
}

// ELU via precomputed exps: e = min(max(u+v,0), eu*ev - 1). No MUFU.
__device__ __forceinline__ u64 elu2x(u64 u2, u64 v2, u64 eu2, u64 ev2, u64 neg1) {
    u64 e;
    asm("{\n\t"
        ".reg .b64 t2, p2, em2;\n\t"
        ".reg .f32 t0, t1, m0, m1, r0, r1;\n\t"
        "add.rn.f32x2 t2, %1, %2;\n\t"
        "mul.rn.f32x2 p2, %3, %4;\n\t"
        "add.rn.f32x2 em2, p2, %5;\n\t"
        "mov.b64 {t0,t1}, t2;\n\t"
        "mov.b64 {m0,m1}, em2;\n\t"
        "max.f32 r0, t0, 0f00000000;\n\t"
        "max.f32 r1, t1, 0f00000000;\n\t"
        "min.f32 r0, r0, m0;\n\t"
        "min.f32 r1, r1, m1;\n\t"
        "mov.b64 %0, {r0,r1};\n\t"
        "}" : "=l"(e) : "l"(u2), "l"(v2), "l"(eu2), "l"(ev2), "l"(neg1));
    return e;
}

// Scratch
__device__ float g_a [B * NN * E];
__device__ float g_u [B * NN * H];
__device__ float g_v [B * NN * H];
__device__ float g_eu[B * NN * H];
__device__ float g_ev[B * NN * H];
__device__ float g_p [B * 16 * H];

// ---------------------------------------------------------------------------
// K1: split-embedding + joint LayerNorm over (N,E). One block per b.
// ---------------------------------------------------------------------------
__global__ __launch_bounds__(256) void k_embed_ln(
    const float* __restrict__ xa, const float* __restrict__ xb,
    const float* __restrict__ Wa, const float* __restrict__ ba,
    const float* __restrict__ Wb, const float* __restrict__ bb,
    const float* __restrict__ g0, const float* __restrict__ b0)
{
    const int b   = blockIdx.x;
    const int tid = threadIdx.x;
    __shared__ float rsum[8], rssq[8];
    __shared__ float s_mean, s_rstd;

    float vals[18];
    float sum = 0.f, ssq = 0.f;

    #pragma unroll
    for (int c = 0; c < 18; ++c) {
        const int idx = tid + c * 256;
        const int n = idx / E;
        const int e = idx - n * E;
        float acc;
        if (n < N1) {
            acc = ba[e];
            const float* xr = xa + (b * N1 + n) * D1;
            #pragma unroll
            for (int k = 0; k < D1; ++k) acc = fmaf(xr[k], Wa[k * E + e], acc);
        } else {
            acc = bb[e];
            const float* xr = xb + (b * N2 + (n - N1)) * D2;
            #pragma unroll
            for (int k = 0; k < D2; ++k) acc = fmaf(xr[k], Wb[k * E + e], acc);
        }
        vals[c] = acc;
        sum += acc;
        ssq = fmaf(acc, acc, ssq);
    }

    #pragma unroll
    for (int o = 16; o; o >>= 1) {
        sum += __shfl_xor_sync(~0u, sum, o);
        ssq += __shfl_xor_sync(~0u, ssq, o);
    }
    const int w = tid >> 5, lane = tid & 31;
    if (lane == 0) { rsum[w] = sum; rssq[w] = ssq; }
    __syncthreads();
    if (tid == 0) {
        float s = 0.f, q = 0.f;
        #pragma unroll
        for (int i = 0; i < 8; ++i) { s += rsum[i]; q += rssq[i]; }
        const float mean = s * (1.f / LNCNT);
        const float var  = fmaf(q, 1.f / LNCNT, -mean * mean);
        s_mean = mean;
        s_rstd = rsqrtf(var + 1e-5f);
    }
    __syncthreads();
    const float mean = s_mean, rstd = s_rstd;

    #pragma unroll
    for (int c = 0; c < 18; ++c) {
        const int idx = tid + c * 256;
        g_a[b * LNCNT + idx] = (vals[c] - mean) * rstd * g0[idx] + b0[idx];
    }
}

// ---------------------------------------------------------------------------
// K2: u = a @ Wg[0:72] + b_g ; v = a @ Wg[72:144]; also eu = e^u, ev = e^v.
// 16 rows/block, f32x2. grid = 512.
// ---------------------------------------------------------------------------
__global__ __launch_bounds__(256) void k_uv(
    const float* __restrict__ Wg, const float* __restrict__ bg)
{
    __shared__ float sa[E * 16];
    const int m0 = blockIdx.x * 16;
    const int h  = threadIdx.x;

    for (int idx = h; idx < E * 16; idx += 256) {
        const int rr = idx / E, k = idx - rr * E;
        sa[k * 16 + rr] = g_a[(m0 + rr) * E + k];
    }
    __syncthreads();

    const float bgh = bg[h];
    u64 uacc[8], vacc[8];
    const u64 bg2 = pk(bgh, bgh);
    #pragma unroll
    for (int p = 0; p < 8; ++p) { uacc[p] = bg2; vacc[p] = 0ull; }

    #pragma unroll 4
    for (int k = 0; k < E; ++k) {
        const ulonglong2* ar = (const ulonglong2*)&sa[k * 16];
        const ulonglong2 q0 = ar[0], q1 = ar[1], q2 = ar[2], q3 = ar[3];
        const u64 av[8] = {q0.x, q0.y, q1.x, q1.y, q2.x, q2.y, q3.x, q3.y};
        const float w0 = Wg[k * H + h];
        const float w1 = Wg[(E + k) * H + h];
        const u64 w02 = pk(w0, w0);
        const u64 w12 = pk(w1, w1);
        #pragma unroll
        for (int p = 0; p < 8; ++p) {
            uacc[p] = fma2(av[p], w02, uacc[p]);
            vacc[p] = fma2(av[p], w12, vacc[p]);
        }
    }

    const float L2E = 1.44269504f;
    #pragma unroll
    for (int p = 0; p < 8; ++p) {
        float lo, hi;
        upk(uacc[p], lo, hi);
        g_u [(m0 + 2 * p) * H + h]     = lo;
        g_u [(m0 + 2 * p + 1) * H + h] = hi;
        g_eu[(m0 + 2 * p) * H + h]     = ex2f(lo * L2E);
        g_eu[(m0 + 2 * p + 1) * H + h] = ex2f(hi * L2E);
        upk(vacc[p], lo, hi);
        g_v [(m0 + 2 * p) * H + h]     = lo;
        g_v [(m0 + 2 * p + 1) * H + h] = hi;
        g_ev[(m0 + 2 * p) * H + h]     = ex2f(lo * L2E);
        g_ev[(m0 + 2 * p + 1) * H + h] = ex2f(hi * L2E);
    }
}

// ---------------------------------------------------------------------------
// K3: pairwise Σ_j LN_H(ELU(u_i + v_j)), j split in halves per block.
// Block = (b, ig, jh): 8 warps = 8 i's, j in [jh*32, jh*32+32).
// Half-warp j-split (lanes 0-15 even local j, 16-31 odd; 16 ch/lane).
// smem: swizzled v-half (32KB) + ev-half (32KB). No MUFU in hot loop.
// __launch_bounds__(256,2): 128-reg budget -> NO SPILLS (the R6 regression
// was (256,3)'s 83-reg cap spilling ru2/re2/acc2 into the hot loop).
// ---------------------------------------------------------------------------
__global__ __launch_bounds__(256, 2) void k_pair(
    const float* __restrict__ lg, const float* __restrict__ lb)
{
    extern __shared__ float sm[];               // [2][32][256]
    float* svv = sm;
    float* sev = sm + 32 * H;

    const int bid  = blockIdx.x;
    const int b    = bid >> 4;
    const int ig   = (bid >> 1) & 7;
    const int jh   = bid & 1;
    const int tid  = threadIdx.x;
    const int w    = tid >> 5;
    const int lane = tid & 31;
    const int half = lane >> 4;
    const int sub  = lane & 15;
    const int ch0  = sub * 16;

    // stage v/ev halves with granule swizzle: float4 q of local row j ->
    // base4[j*64 + (q&3)*16 + (q>>2)]
    {
        const float4* vb = (const float4*)(g_v  + (b * NN + jh * 32) * H);
        const float4* eb = (const float4*)(g_ev + (b * NN + jh * 32) * H);
        float4* s4v = (float4*)svv;
        float4* s4e = (float4*)sev;
        #pragma unroll
        for (int c = 0; c < 8; ++c) {
            const int g = tid + c * 256;        // < 2048
            const int j = g >> 6;
            const int q = g & 63;
            const int off = j * 64 + (q & 3) * 16 + (q >> 2);
            s4v[off] = vb[g];
            s4e[off] = eb[g];
        }
    }

    const int m = b * NN + ig * 8 + w;

    u64 ru2[8], re2[8];
    {
        const ulonglong2* uu = (const ulonglong2*)(g_u + m * H + ch0);
        const ulonglong2 a0 = uu[0], a1 = uu[1], a2 = uu[2], a3 = uu[3];
        ru2[0] = a0.x; ru2[1] = a0.y; ru2[2] = a1.x; ru2[3] = a1.y;
        ru2[4] = a2.x; ru2[5] = a2.y; ru2[6] = a3.x; ru2[7] = a3.y;
        const ulonglong2* ee = (const ulonglong2*)(g_eu + m * H + ch0);
        const ulonglong2 b0 = ee[0], b1 = ee[1], b2 = ee[2], b3 = ee[3];
        re2[0] = b0.x; re2[1] = b0.y; re2[2] = b1.x; re2[3] = b1.y;
        re2[4] = b2.x; re2[5] = b2.y; re2[6] = b3.x; re2[7] = b3.y;
    }
    u64 acc2[8];
    const u64 NEG1 = pk(-1.f, -1.f);
    #pragma unroll
    for (int p = 0; p < 8; ++p) acc2[p] = 0ull;
    float smA = 0.f;

    __syncthreads();

    #pragma unroll 2
    for (int s = 0; s < 16; ++s) {
        const int jl = 2 * s + half;            // local row 0..31
        const ulonglong2* vr = (const ulonglong2*)(svv + jl * H);
        const ulonglong2* er = (const ulonglong2*)(sev + jl * H);

        u64 e2[8];
        {
            const ulonglong2 v0 = vr[sub],      e0 = er[sub];
            const ulonglong2 v1 = vr[16 + sub], e1 = er[16 + sub];
            const ulonglong2 v2 = vr[32 + sub], e2q = er[32 + sub];
            const ulonglong2 v3 = vr[48 + sub], e3 = er[48 + sub];
            e2[0] = elu2x(ru2[0], v0.x, re2[0], e0.x, NEG1);
            e2[1] = elu2x(ru2[1], v0.y, re2[1], e0.y, NEG1);
            e2[2] = elu2x(ru2[2], v1.x, re2[2], e1.x, NEG1);
            e2[3] = elu2x(ru2[3], v1.y, re2[3], e1.y, NEG1);
            e2[4] = elu2x(ru2[4], v2.x, re2[4], e2q.x, NEG1);
            e2[5] = elu2x(ru2[5], v2.y, re2[5], e2q.y, NEG1);
            e2[6] = elu2x(ru2[6], v3.x, re2[6], e3.x, NEG1);
            e2[7] = elu2x(ru2[7], v3.y, re2[7], e3.y, NEG1);
        }

        u64 se = add2(add2(add2(e2[0], e2[1]), add2(e2[2], e2[3])),
                      add2(add2(e2[4], e2[5]), add2(e2[6], e2[7])));
        u64 sq = mul2(e2[0], e2[0]);
        sq = fma2(e2[1], e2[1], sq); sq = fma2(e2[2], e2[2], sq);
        sq = fma2(e2[3], e2[3], sq); sq = fma2(e2[4], e2[4], sq);
        sq = fma2(e2[5], e2[5], sq); sq = fma2(e2[6], e2[6], sq);
        sq = fma2(e2[7], e2[7], sq);
        float selo, sehi, sqlo, sqhi;
        upk(se, selo, sehi); upk(sq, sqlo, sqhi);
        float sum = selo + sehi;
        float ssq = sqlo + sqhi;

        // butterfly within 16-lane half
        #pragma unroll
        for (int o = 8; o; o >>= 1) {
            sum += __shfl_xor_sync(~0u, sum, o);
            ssq += __shfl_xor_sync(~0u, ssq, o);
        }
        const float mean = sum * (1.f / H);
        const float var  = fmaf(ssq, 1.f / H, -mean * mean);
        const float A    = rsqrtf(var + 1e-5f);
        smA = fmaf(mean, A, smA);
        const u64 A2 = pk(A, A);
        #pragma unroll
        for (int p = 0; p < 8; ++p) acc2[p] = fma2(e2[p], A2, acc2[p]);
    }

    // merge even/odd-j halves
    #pragma unroll
    for (int p = 0; p < 8; ++p) acc2[p] = add2(acc2[p], shfl_xor_u64(acc2[p], 16));
    smA += __shfl_xor_sync(~0u, smA, 16);

    __syncthreads();                       // all warps done reading smem
    if (half == 0) {
        const u64 nsmA = pk(-smA, -smA);
        u64* dst = (u64*)&svv[w * H + ch0];
        #pragma unroll
        for (int p = 0; p < 8; ++p) dst[p] = add2(acc2[p], nsmA);
    }
    __syncthreads();
    {
        float s = 0.f;
        #pragma unroll
        for (int ww = 0; ww < 8; ++ww) s += svv[ww * H + tid];
        // this block covers 8 i * 32 j = 256 (i,j) pairs -> 256 * beta
        g_p[bid * H + tid] = fmaf(lg[tid], s, 256.f * lb[tid]);
    }
}

// ---------------------------------------------------------------------------
// K4: s[b] = Σ 16 partials; out = ELU(s @ W_f + b_f).
// 4-way F-split: 512 blocks, 256 thr.
// ---------------------------------------------------------------------------
__global__ __launch_bounds__(256) void k_final(
    const float* __restrict__ Wf, const float* __restrict__ bf,
    float* __restrict__ out)
{
    const int bid  = blockIdx.x;
    const int b    = bid >> 2;
    const int fq   = bid & 3;
    const int tid  = threadIdx.x;
    const int w    = tid >> 5;
    const int lane = tid & 31;
    __shared__ float ss[H];
    __shared__ float part[8][32];

    {
        float s = 0.f;
        #pragma unroll
        for (int ig = 0; ig < 16; ++ig) s += g_p[(b * 16 + ig) * H + tid];
        ss[tid] = s;
    }
    __syncthreads();

    const int f  = fq * 32 + lane;
    const int h0 = w * 32;
    float a0 = 0.f, a1 = 0.f, a2 = 0.f, a3 = 0.f;
    #pragma unroll
    for (int hh = 0; hh < 32; hh += 4) {
        a0 = fmaf(ss[h0 + hh + 0], Wf[(h0 + hh + 0) * F + f], a0);
        a1 = fmaf(ss[h0 + hh + 1], Wf[(h0 + hh + 1) * F + f], a1);
        a2 = fmaf(ss[h0 + hh + 2], Wf[(h0 + hh + 2) * F + f], a2);
        a3 = fmaf(ss[h0 + hh + 3], Wf[(h0 + hh + 3) * F + f], a3);
    }
    part[w][lane] = (a0 + a1) + (a2 + a3);
    __syncthreads();

    if (w == 0) {
        float o = bf[f];
        #pragma unroll
        for (int k = 0; k < 8; ++k) o += part[k][lane];
        out[b * F + f] = (o > 0.f) ? o : expm1f(o);
    }
}

// ---------------------------------------------------------------------------
extern "C" void kernel_launch(void* const* d_in, const int* in_sizes, int n_in,
                              void* d_out, int out_size)
{
    const float* x_a   = (const float*)d_in[0];
    const float* x_b   = (const float*)d_in[1];
    const float* W_a   = (const float*)d_in[2];
    const float* b_a   = (const float*)d_in[3];
    const float* W_b   = (const float*)d_in[4];
    const float* b_b   = (const float*)d_in[5];
    const float* ln0_g = (const float*)d_in[6];
    const float* ln0_b = (const float*)d_in[7];
    const float* W_g   = (const float*)d_in[8];
    const float* b_g   = (const float*)d_in[9];
    const float* lng_g = (const float*)d_in[10];
    const float* lng_b = (const float*)d_in[11];
    const float* W_f   = (const float*)d_in[12];
    const float* b_f   = (const float*)d_in[13];
    float* out = (float*)d_out;

    k_embed_ln<<<B, 256>>>(x_a, x_b, W_a, b_a, W_b, b_b, ln0_g, ln0_b);
    k_uv<<<B * NN / 16, 256>>>(W_g, b_g);

    const size_t smem = 2 * 32 * H * sizeof(float);   // 64 KB
    cudaFuncSetAttribute(k_pair, cudaFuncAttributeMaxDynamicSharedMemorySize, (int)smem);
    k_pair<<<B * 16, 256, smem>>>(lng_g, lng_b);

    k_final<<<B * 4, 256>>>(W_f, b_f, out);
}

// round 8
// speedup vs baseline: 1.2388x; 1.2055x over previous
#include <cuda_runtime.h>
#include <cuda_bf16.h>

#define B    128
#define N1   32
#define N2   32
#define D1   23
#define D2   13
#define NN   64
#define E    72
#define H    256
#define F    128
#define LNCNT 4608

typedef unsigned long long u64;

// ---- f32x2 packed helpers (sm_103a) ----
__device__ __forceinline__ u64 pk(float lo, float hi) {
    u64 r; asm("mov.b64 %0, {%1,%2};" : "=l"(r) : "f"(lo), "f"(hi)); return r;
}
__device__ __forceinline__ void upk(u64 x, float& lo, float& hi) {
    asm("mov.b64 {%0,%1}, %2;" : "=f"(lo), "=f"(hi) : "l"(x));
}
__device__ __forceinline__ u64 add2(u64 a, u64 b) {
    u64 d; asm("add.rn.f32x2 %0,%1,%2;" : "=l"(d) : "l"(a), "l"(b)); return d;
}
__device__ __forceinline__ u64 mul2(u64 a, u64 b) {
    u64 d; asm("mul.rn.f32x2 %0,%1,%2;" : "=l"(d) : "l"(a), "l"(b)); return d;
}
__device__ __forceinline__ u64 fma2(u64 a, u64 b, u64 c) {
    u64 d; asm("fma.rn.f32x2 %0,%1,%2,%3;" : "=l"(d) : "l"(a), "l"(b), "l"(c)); return d;
}
__device__ __forceinline__ float ex2f(float x) {
    float r; asm("ex2.approx.ftz.f32 %0, %1;" : "=f"(r) : "f"(x)); return r;
}
__device__ __forceinline__ u64 shfl_xor_u64(u64 x, int o) {
    float lo, hi; upk(x, lo, hi);
    lo = __shfl_xor_sync(~0u, lo, o);
    hi = __shfl_xor_sync(~0u, hi, o);
    return pk(lo, hi);
}

// Fused packed ELU (MUFU runs on its own pipe, overlaps issue):
// e = min(max(t,0), e^t - 1), t = u + v.
__device__ __forceinline__ u64 elu2(u64 u2, u64 v2, u64 l2e, u64 neg1) {
    u64 e;
    asm("{\n\t"
        ".reg .b64 t2, x2, em2;\n\t"
        ".reg .f32 t0, t1, x0, x1, m0, m1, r0, r1;\n\t"
        "add.rn.f32x2 t2, %1, %2;\n\t"
        "mul.rn.f32x2 x2, t2, %3;\n\t"
        "mov.b64 {x0,x1}, x2;\n\t"
        "ex2.approx.ftz.f32 x0, x0;\n\t"
        "ex2.approx.ftz.f32 x1, x1;\n\t"
        "mov.b64 x2, {x0,x1};\n\t"
        "add.rn.f32x2 em2, x2, %4;\n\t"
        "mov.b64 {m0,m1}, em2;\n\t"
        "mov.b64 {t0,t1}, t2;\n\t"
        "max.f32 r0, t0, 0f00000000;\n\t"
        "max.f32 r1, t1, 0f00000000;\n\t"
        "min.f32 r0, r0, m0;\n\t"
        "min.f32 r1, r1, m1;\n\t"
        "mov.b64 %0, {r0,r1};\n\t"
        "}" : "=l"(e) : "l"(u2), "l"(v2), "l"(l2e), "l"(neg1));
    return e;
}

// Scratch
__device__ float g_a[B * NN * E];
__device__ float g_u[B * NN * H];
__device__ float g_v[B * NN * H];
__device__ float g_p[B * 16 * H];

// ---------------------------------------------------------------------------
// K1: split-embedding + joint LayerNorm over (N,E). One block per b.
// Weights staged in smem (they were ~414 redundant LDG per thread before).
// ---------------------------------------------------------------------------
__global__ __launch_bounds__(256) void k_embed_ln(
    const float* __restrict__ xa, const float* __restrict__ xb,
    const float* __restrict__ Wa, const float* __restrict__ ba,
    const float* __restrict__ Wb, const float* __restrict__ bb,
    const float* __restrict__ g0, const float* __restrict__ b0)
{
    const int b   = blockIdx.x;
    const int tid = threadIdx.x;
    __shared__ float sWa[D1 * E];      // 1656
    __shared__ float sWb[D2 * E];      // 936
    __shared__ float sba[E], sbb[E];
    __shared__ float rsum[8], rssq[8];
    __shared__ float s_mean, s_rstd;

    for (int i = tid; i < D1 * E; i += 256) sWa[i] = Wa[i];
    for (int i = tid; i < D2 * E; i += 256) sWb[i] = Wb[i];
    if (tid < E) { sba[tid] = ba[tid]; sbb[tid] = bb[tid]; }
    __syncthreads();

    float vals[18];
    float sum = 0.f, ssq = 0.f;

    #pragma unroll
    for (int c = 0; c < 18; ++c) {
        const int idx = tid + c * 256;
        const int n = idx / E;
        const int e = idx - n * E;
        float acc;
        if (n < N1) {
            acc = sba[e];
            const float* xr = xa + (b * N1 + n) * D1;
            #pragma unroll
            for (int k = 0; k < D1; ++k) acc = fmaf(xr[k], sWa[k * E + e], acc);
        } else {
            acc = sbb[e];
            const float* xr = xb + (b * N2 + (n - N1)) * D2;
            #pragma unroll
            for (int k = 0; k < D2; ++k) acc = fmaf(xr[k], sWb[k * E + e], acc);
        }
        vals[c] = acc;
        sum += acc;
        ssq = fmaf(acc, acc, ssq);
    }

    #pragma unroll
    for (int o = 16; o; o >>= 1) {
        sum += __shfl_xor_sync(~0u, sum, o);
        ssq += __shfl_xor_sync(~0u, ssq, o);
    }
    const int w = tid >> 5, lane = tid & 31;
    if (lane == 0) { rsum[w] = sum; rssq[w] = ssq; }
    __syncthreads();
    if (tid == 0) {
        float s = 0.f, q = 0.f;
        #pragma unroll
        for (int i = 0; i < 8; ++i) { s += rsum[i]; q += rssq[i]; }
        const float mean = s * (1.f / LNCNT);
        const float var  = fmaf(q, 1.f / LNCNT, -mean * mean);
        s_mean = mean;
        s_rstd = rsqrtf(var + 1e-5f);
    }
    __syncthreads();
    const float mean = s_mean, rstd = s_rstd;

    #pragma unroll
    for (int c = 0; c < 18; ++c) {
        const int idx = tid + c * 256;
        g_a[b * LNCNT + idx] = (vals[c] - mean) * rstd * g0[idx] + b0[idx];
    }
}

// ---------------------------------------------------------------------------
// K2: u = a @ Wg[0:72] + b_g ; v = a @ Wg[72:144]. 16 rows/block, f32x2.
// (Near its 302M-FMA floor; unchanged.)
// ---------------------------------------------------------------------------
__global__ __launch_bounds__(256) void k_uv(
    const float* __restrict__ Wg, const float* __restrict__ bg)
{
    __shared__ float sa[E * 16];
    const int m0 = blockIdx.x * 16;
    const int h  = threadIdx.x;

    for (int idx = h; idx < E * 16; idx += 256) {
        const int rr = idx / E, k = idx - rr * E;
        sa[k * 16 + rr] = g_a[(m0 + rr) * E + k];
    }
    __syncthreads();

    const float bgh = bg[h];
    u64 uacc[8], vacc[8];
    const u64 bg2 = pk(bgh, bgh);
    #pragma unroll
    for (int p = 0; p < 8; ++p) { uacc[p] = bg2; vacc[p] = 0ull; }

    #pragma unroll 4
    for (int k = 0; k < E; ++k) {
        const ulonglong2* ar = (const ulonglong2*)&sa[k * 16];
        const ulonglong2 q0 = ar[0], q1 = ar[1], q2 = ar[2], q3 = ar[3];
        const u64 av[8] = {q0.x, q0.y, q1.x, q1.y, q2.x, q2.y, q3.x, q3.y};
        const float w0 = Wg[k * H + h];
        const float w1 = Wg[(E + k) * H + h];
        const u64 w02 = pk(w0, w0);
        const u64 w12 = pk(w1, w1);
        #pragma unroll
        for (int p = 0; p < 8; ++p) {
            uacc[p] = fma2(av[p], w02, uacc[p]);
            vacc[p] = fma2(av[p], w12, vacc[p]);
        }
    }

    #pragma unroll
    for (int p = 0; p < 8; ++p) {
        float lo, hi;
        upk(uacc[p], lo, hi);
        g_u[(m0 + 2 * p) * H + h]     = lo;
        g_u[(m0 + 2 * p + 1) * H + h] = hi;
        upk(vacc[p], lo, hi);
        g_v[(m0 + 2 * p) * H + h]     = lo;
        g_v[(m0 + 2 * p + 1) * H + h] = hi;
    }
}

// ---------------------------------------------------------------------------
// K3: pairwise Σ_j LN_H(ELU(u_i + v_j)). R5 math (MUFU elu2, single v
// stream) + half-j blocks: 32 j's per block -> 32KB smem -> (256,3) gives
// 6 warps/SMSP for latency cover. Depth-1 body (live regs ~72 < 83 cap).
// Half-warp j-split: lanes 0-15 even local j, 16-31 odd; 16 ch/lane.
// ---------------------------------------------------------------------------
__global__ __launch_bounds__(256, 3) void k_pair(
    const float* __restrict__ lg, const float* __restrict__ lb)
{
    extern __shared__ float sv[];               // [32][256] swizzled v-half
    const int bid  = blockIdx.x;
    const int b    = bid >> 4;
    const int ig   = (bid >> 1) & 7;
    const int jh   = bid & 1;
    const int tid  = threadIdx.x;
    const int w    = tid >> 5;
    const int lane = tid & 31;
    const int half = lane >> 4;
    const int sub  = lane & 15;
    const int ch0  = sub * 16;

    // stage v half with granule swizzle: float4 q of local row j ->
    // sv4[j*64 + (q&3)*16 + (q>>2)]
    {
        const float4* vb = (const float4*)(g_v + (b * NN + jh * 32) * H);
        float4* s4 = (float4*)sv;
        #pragma unroll
        for (int c = 0; c < 8; ++c) {
            const int g = tid + c * 256;        // < 2048
            const int j = g >> 6;
            const int q = g & 63;
            s4[j * 64 + (q & 3) * 16 + (q >> 2)] = vb[g];
        }
    }

    const int m = b * NN + ig * 8 + w;

    u64 ru2[8];
    {
        const ulonglong2* uu = (const ulonglong2*)(g_u + m * H + ch0);
        const ulonglong2 a0 = uu[0], a1 = uu[1], a2 = uu[2], a3 = uu[3];
        ru2[0] = a0.x; ru2[1] = a0.y; ru2[2] = a1.x; ru2[3] = a1.y;
        ru2[4] = a2.x; ru2[5] = a2.y; ru2[6] = a3.x; ru2[7] = a3.y;
    }
    u64 acc2[8];
    const u64 L2E  = pk(1.44269504f, 1.44269504f);
    const u64 NEG1 = pk(-1.f, -1.f);
    #pragma unroll
    for (int p = 0; p < 8; ++p) acc2[p] = 0ull;
    float smA = 0.f;

    __syncthreads();

    #pragma unroll 2
    for (int s = 0; s < 16; ++s) {
        const int jl = 2 * s + half;            // local row 0..31
        const ulonglong2* vr = (const ulonglong2*)(sv + jl * H);

        u64 e2[8];
        {
            const ulonglong2 v0 = vr[sub];
            const ulonglong2 v1 = vr[16 + sub];
            const ulonglong2 v2 = vr[32 + sub];
            const ulonglong2 v3 = vr[48 + sub];
            e2[0] = elu2(ru2[0], v0.x, L2E, NEG1);
            e2[1] = elu2(ru2[1], v0.y, L2E, NEG1);
            e2[2] = elu2(ru2[2], v1.x, L2E, NEG1);
            e2[3] = elu2(ru2[3], v1.y, L2E, NEG1);
            e2[4] = elu2(ru2[4], v2.x, L2E, NEG1);
            e2[5] = elu2(ru2[5], v2.y, L2E, NEG1);
            e2[6] = elu2(ru2[6], v3.x, L2E, NEG1);
            e2[7] = elu2(ru2[7], v3.y, L2E, NEG1);
        }

        u64 se = add2(add2(add2(e2[0], e2[1]), add2(e2[2], e2[3])),
                      add2(add2(e2[4], e2[5]), add2(e2[6], e2[7])));
        u64 sq = mul2(e2[0], e2[0]);
        sq = fma2(e2[1], e2[1], sq); sq = fma2(e2[2], e2[2], sq);
        sq = fma2(e2[3], e2[3], sq); sq = fma2(e2[4], e2[4], sq);
        sq = fma2(e2[5], e2[5], sq); sq = fma2(e2[6], e2[6], sq);
        sq = fma2(e2[7], e2[7], sq);
        float selo, sehi, sqlo, sqhi;
        upk(se, selo, sehi); upk(sq, sqlo, sqhi);
        float sum = selo + sehi;
        float ssq = sqlo + sqhi;

        // butterfly within 16-lane half
        #pragma unroll
        for (int o = 8; o; o >>= 1) {
            sum += __shfl_xor_sync(~0u, sum, o);
            ssq += __shfl_xor_sync(~0u, ssq, o);
        }
        const float mean = sum * (1.f / H);
        const float var  = fmaf(ssq, 1.f / H, -mean * mean);
        const float A    = rsqrtf(var + 1e-5f);
        smA = fmaf(mean, A, smA);
        const u64 A2 = pk(A, A);
        #pragma unroll
        for (int p = 0; p < 8; ++p) acc2[p] = fma2(e2[p], A2, acc2[p]);
    }

    // merge even/odd-j halves
    #pragma unroll
    for (int p = 0; p < 8; ++p) acc2[p] = add2(acc2[p], shfl_xor_u64(acc2[p], 16));
    smA += __shfl_xor_sync(~0u, smA, 16);

    __syncthreads();                       // all warps done reading sv
    if (half == 0) {
        const u64 nsmA = pk(-smA, -smA);
        u64* dst = (u64*)&sv[w * H + ch0];
        #pragma unroll
        for (int p = 0; p < 8; ++p) dst[p] = add2(acc2[p], nsmA);
    }
    __syncthreads();
    {
        float s = 0.f;
        #pragma unroll
        for (int ww = 0; ww < 8; ++ww) s += sv[ww * H + tid];
        // block covers 8 i * 32 j = 256 (i,j) pairs -> 256 * beta
        g_p[bid * H + tid] = fmaf(lg[tid], s, 256.f * lb[tid]);
    }
}

// ---------------------------------------------------------------------------
// K4: s[b] = Σ 16 partials; out = ELU(s @ W_f + b_f). 4-way F-split.
// ---------------------------------------------------------------------------
__global__ __launch_bounds__(256) void k_final(
    const float* __restrict__ Wf, const float* __restrict__ bf,
    float* __restrict__ out)
{
    const int bid  = blockIdx.x;
    const int b    = bid >> 2;
    const int fq   = bid & 3;
    const int tid  = threadIdx.x;
    const int w    = tid >> 5;
    const int lane = tid & 31;
    __shared__ float ss[H];
    __shared__ float part[8][32];

    {
        float s = 0.f;
        #pragma unroll
        for (int ig = 0; ig < 16; ++ig) s += g_p[(b * 16 + ig) * H + tid];
        ss[tid] = s;
    }
    __syncthreads();

    const int f  = fq * 32 + lane;
    const int h0 = w * 32;
    float a0 = 0.f, a1 = 0.f, a2 = 0.f, a3 = 0.f;
    #pragma unroll
    for (int hh = 0; hh < 32; hh += 4) {
        a0 = fmaf(ss[h0 + hh + 0], Wf[(h0 + hh + 0) * F + f], a0);
        a1 = fmaf(ss[h0 + hh + 1], Wf[(h0 + hh + 1) * F + f], a1);
        a2 = fmaf(ss[h0 + hh + 2], Wf[(h0 + hh + 2) * F + f], a2);
        a3 = fmaf(ss[h0 + hh + 3], Wf[(h0 + hh + 3) * F + f], a3);
    }
    part[w][lane] = (a0 + a1) + (a2 + a3);
    __syncthreads();

    if (w == 0) {
        float o = bf[f];
        #pragma unroll
        for (int k = 0; k < 8; ++k) o += part[k][lane];
        out[b * F + f] = (o > 0.f) ? o : expm1f(o);
    }
}

// ---------------------------------------------------------------------------
extern "C" void kernel_launch(void* const* d_in, const int* in_sizes, int n_in,
                              void* d_out, int out_size)
{
    const float* x_a   = (const float*)d_in[0];
    const float* x_b   = (const float*)d_in[1];
    const float* W_a   = (const float*)d_in[2];
    const float* b_a   = (const float*)d_in[3];
    const float* W_b   = (const float*)d_in[4];
    const float* b_b   = (const float*)d_in[5];
    const float* ln0_g = (const float*)d_in[6];
    const float* ln0_b = (const float*)d_in[7];
    const float* W_g   = (const float*)d_in[8];
    const float* b_g   = (const float*)d_in[9];
    const float* lng_g = (const float*)d_in[10];
    const float* lng_b = (const float*)d_in[11];
    const float* W_f   = (const float*)d_in[12];
    const float* b_f   = (const float*)d_in[13];
    float* out = (float*)d_out;

    k_embed_ln<<<B, 256>>>(x_a, x_b, W_a, b_a, W_b, b_b, ln0_g, ln0_b);
    k_uv<<<B * NN / 16, 256>>>(W_g, b_g);

    const size_t smem = 32 * H * sizeof(float);   // 32 KB
    cudaFuncSetAttribute(k_pair, cudaFuncAttributeMaxDynamicSharedMemorySize, (int)smem);
    k_pair<<<B * 16, 256, smem>>>(lng_g, lng_b);

    k_final<<<B * 4, 256>>>(W_f, b_f, out);
}

// round 9
// speedup vs baseline: 1.2681x; 1.0236x over previous
#include <cuda_runtime.h>
#include <cuda_bf16.h>

#define B    128
#define N1   32
#define N2   32
#define D1   23
#define D2   13
#define NN   64
#define E    72
#define H    256
#define F    128
#define LNCNT 4608

typedef unsigned long long u64;

// ---- f32x2 packed helpers (sm_103a) ----
__device__ __forceinline__ u64 pk(float lo, float hi) {
    u64 r; asm("mov.b64 %0, {%1,%2};" : "=l"(r) : "f"(lo), "f"(hi)); return r;
}
__device__ __forceinline__ void upk(u64 x, float& lo, float& hi) {
    asm("mov.b64 {%0,%1}, %2;" : "=f"(lo), "=f"(hi) : "l"(x));
}
__device__ __forceinline__ u64 add2(u64 a, u64 b) {
    u64 d; asm("add.rn.f32x2 %0,%1,%2;" : "=l"(d) : "l"(a), "l"(b)); return d;
}
__device__ __forceinline__ u64 mul2(u64 a, u64 b) {
    u64 d; asm("mul.rn.f32x2 %0,%1,%2;" : "=l"(d) : "l"(a), "l"(b)); return d;
}
__device__ __forceinline__ u64 fma2(u64 a, u64 b, u64 c) {
    u64 d; asm("fma.rn.f32x2 %0,%1,%2,%3;" : "=l"(d) : "l"(a), "l"(b), "l"(c)); return d;
}
__device__ __forceinline__ float ex2f(float x) {
    float r; asm("ex2.approx.ftz.f32 %0, %1;" : "=f"(r) : "f"(x)); return r;
}

// Fused packed ELU: e = min(max(t,0), e^t - 1), t = u + v.
__device__ __forceinline__ u64 elu2(u64 u2, u64 v2, u64 l2e, u64 neg1) {
    u64 e;
    asm("{\n\t"
        ".reg .b64 t2, x2, em2;\n\t"
        ".reg .f32 t0, t1, x0, x1, m0, m1, r0, r1;\n\t"
        "add.rn.f32x2 t2, %1, %2;\n\t"
        "mul.rn.f32x2 x2, t2, %3;\n\t"
        "mov.b64 {x0,x1}, x2;\n\t"
        "ex2.approx.ftz.f32 x0, x0;\n\t"
        "ex2.approx.ftz.f32 x1, x1;\n\t"
        "mov.b64 x2, {x0,x1};\n\t"
        "add.rn.f32x2 em2, x2, %4;\n\t"
        "mov.b64 {m0,m1}, em2;\n\t"
        "mov.b64 {t0,t1}, t2;\n\t"
        "max.f32 r0, t0, 0f00000000;\n\t"
        "max.f32 r1, t1, 0f00000000;\n\t"
        "min.f32 r0, r0, m0;\n\t"
        "min.f32 r1, r1, m1;\n\t"
        "mov.b64 %0, {r0,r1};\n\t"
        "}" : "=l"(e) : "l"(u2), "l"(v2), "l"(l2e), "l"(neg1));
    return e;
}

// Scratch
__device__ float g_a[B * NN * E];
__device__ float g_u[B * NN * H];
__device__ float g_v[B * NN * H];
__device__ float g_p[B * 32 * H];

// ---------------------------------------------------------------------------
// K1: split-embedding + joint LayerNorm over (N,E). One block per b.
// Weights staged in smem.
// ---------------------------------------------------------------------------
__global__ __launch_bounds__(256) void k_embed_ln(
    const float* __restrict__ xa, const float* __restrict__ xb,
    const float* __restrict__ Wa, const float* __restrict__ ba,
    const float* __restrict__ Wb, const float* __restrict__ bb,
    const float* __restrict__ g0, const float* __restrict__ b0)
{
    const int b   = blockIdx.x;
    const int tid = threadIdx.x;
    __shared__ float sWa[D1 * E];
    __shared__ float sWb[D2 * E];
    __shared__ float sba[E], sbb[E];
    __shared__ float rsum[8], rssq[8];
    __shared__ float s_mean, s_rstd;

    for (int i = tid; i < D1 * E; i += 256) sWa[i] = Wa[i];
    for (int i = tid; i < D2 * E; i += 256) sWb[i] = Wb[i];
    if (tid < E) { sba[tid] = ba[tid]; sbb[tid] = bb[tid]; }
    __syncthreads();

    float vals[18];
    float sum = 0.f, ssq = 0.f;

    #pragma unroll
    for (int c = 0; c < 18; ++c) {
        const int idx = tid + c * 256;
        const int n = idx / E;
        const int e = idx - n * E;
        float acc;
        if (n < N1) {
            acc = sba[e];
            const float* xr = xa + (b * N1 + n) * D1;
            #pragma unroll
            for (int k = 0; k < D1; ++k) acc = fmaf(xr[k], sWa[k * E + e], acc);
        } else {
            acc = sbb[e];
            const float* xr = xb + (b * N2 + (n - N1)) * D2;
            #pragma unroll
            for (int k = 0; k < D2; ++k) acc = fmaf(xr[k], sWb[k * E + e], acc);
        }
        vals[c] = acc;
        sum += acc;
        ssq = fmaf(acc, acc, ssq);
    }

    #pragma unroll
    for (int o = 16; o; o >>= 1) {
        sum += __shfl_xor_sync(~0u, sum, o);
        ssq += __shfl_xor_sync(~0u, ssq, o);
    }
    const int w = tid >> 5, lane = tid & 31;
    if (lane == 0) { rsum[w] = sum; rssq[w] = ssq; }
    __syncthreads();
    if (tid == 0) {
        float s = 0.f, q = 0.f;
        #pragma unroll
        for (int i = 0; i < 8; ++i) { s += rsum[i]; q += rssq[i]; }
        const float mean = s * (1.f / LNCNT);
        const float var  = fmaf(q, 1.f / LNCNT, -mean * mean);
        s_mean = mean;
        s_rstd = rsqrtf(var + 1e-5f);
    }
    __syncthreads();
    const float mean = s_mean, rstd = s_rstd;

    #pragma unroll
    for (int c = 0; c < 18; ++c) {
        const int idx = tid + c * 256;
        g_a[b * LNCNT + idx] = (vals[c] - mean) * rstd * g0[idx] + b0[idx];
    }
}

// ---------------------------------------------------------------------------
// K2: u = a @ Wg[0:72] + b_g ; v = a @ Wg[72:144]. 16 rows/block, f32x2.
// ---------------------------------------------------------------------------
__global__ __launch_bounds__(256) void k_uv(
    const float* __restrict__ Wg, const float* __restrict__ bg)
{
    __shared__ float sa[E * 16];
    const int m0 = blockIdx.x * 16;
    const int h  = threadIdx.x;

    for (int idx = h; idx < E * 16; idx += 256) {
        const int rr = idx / E, k = idx - rr * E;
        sa[k * 16 + rr] = g_a[(m0 + rr) * E + k];
    }
    __syncthreads();

    const float bgh = bg[h];
    u64 uacc[8], vacc[8];
    const u64 bg2 = pk(bgh, bgh);
    #pragma unroll
    for (int p = 0; p < 8; ++p) { uacc[p] = bg2; vacc[p] = 0ull; }

    #pragma unroll 4
    for (int k = 0; k < E; ++k) {
        const ulonglong2* ar = (const ulonglong2*)&sa[k * 16];
        const ulonglong2 q0 = ar[0], q1 = ar[1], q2 = ar[2], q3 = ar[3];
        const u64 av[8] = {q0.x, q0.y, q1.x, q1.y, q2.x, q2.y, q3.x, q3.y};
        const float w0 = Wg[k * H + h];
        const float w1 = Wg[(E + k) * H + h];
        const u64 w02 = pk(w0, w0);
        const u64 w12 = pk(w1, w1);
        #pragma unroll
        for (int p = 0; p < 8; ++p) {
            uacc[p] = fma2(av[p], w02, uacc[p]);
            vacc[p] = fma2(av[p], w12, vacc[p]);
        }
    }

    #pragma unroll
    for (int p = 0; p < 8; ++p) {
        float lo, hi;
        upk(uacc[p], lo, hi);
        g_u[(m0 + 2 * p) * H + h]     = lo;
        g_u[(m0 + 2 * p + 1) * H + h] = hi;
        upk(vacc[p], lo, hi);
        g_v[(m0 + 2 * p) * H + h]     = lo;
        g_v[(m0 + 2 * p + 1) * H + h] = hi;
    }
}

// ---------------------------------------------------------------------------
// K3: pairwise Σ_j LN_H(ELU(u_i + v_j)).
// LIGHT layout for occupancy: 8 ch/lane, full-warp butterfly per j.
// Block = (b, ig, jq): 8 warps = 8 i's, 16 j's staged (16KB smem).
// __launch_bounds__(256,4): 64-reg cap (live ~44) -> 4 blocks/SM
// = 8 warps/SMSP for latency cover.  Grid = B*32 = 4096.
// smem layout: float4 #q of row j at s4[j*64 + (q&1)*32 + (q>>1)]
//   -> each of the lane's two LDS.128 reads a 128B-contiguous phase.
// ---------------------------------------------------------------------------
__global__ __launch_bounds__(256, 4) void k_pair(
    const float* __restrict__ lg, const float* __restrict__ lb)
{
    extern __shared__ float sv[];               // [16][256] swizzled v-quarter
    const int bid  = blockIdx.x;
    const int b    = bid >> 5;
    const int ig   = (bid >> 2) & 7;
    const int jq   = bid & 3;
    const int tid  = threadIdx.x;
    const int w    = tid >> 5;
    const int lane = tid & 31;

    // stage 16 rows of v with pair-interleave swizzle
    {
        const float4* vb = (const float4*)(g_v + (b * NN + jq * 16) * H);
        float4* s4 = (float4*)sv;
        #pragma unroll
        for (int c = 0; c < 4; ++c) {
            const int g = tid + c * 256;        // < 1024
            const int j = g >> 6;
            const int q = g & 63;
            s4[j * 64 + (q & 1) * 32 + (q >> 1)] = vb[g];
        }
    }

    const int m = b * NN + ig * 8 + w;

    u64 ru2[4];
    {
        // channels [8*lane, 8*lane+8)
        const ulonglong2* uu = (const ulonglong2*)(g_u + m * H + lane * 8);
        const ulonglong2 a0 = uu[0], a1 = uu[1];
        ru2[0] = a0.x; ru2[1] = a0.y; ru2[2] = a1.x; ru2[3] = a1.y;
    }
    u64 acc2[4];
    const u64 L2E  = pk(1.44269504f, 1.44269504f);
    const u64 NEG1 = pk(-1.f, -1.f);
    #pragma unroll
    for (int p = 0; p < 4; ++p) acc2[p] = 0ull;
    float smA = 0.f;

    __syncthreads();

    #pragma unroll 4
    for (int s = 0; s < 16; ++s) {
        const ulonglong2* vr = (const ulonglong2*)(sv + s * H);
        // lane's channels: float4 #2*lane at [lane], #2*lane+1 at [32+lane]
        const ulonglong2 q0 = vr[lane];
        const ulonglong2 q1 = vr[32 + lane];

        u64 e2[4];
        e2[0] = elu2(ru2[0], q0.x, L2E, NEG1);
        e2[1] = elu2(ru2[1], q0.y, L2E, NEG1);
        e2[2] = elu2(ru2[2], q1.x, L2E, NEG1);
        e2[3] = elu2(ru2[3], q1.y, L2E, NEG1);

        u64 se = add2(add2(e2[0], e2[1]), add2(e2[2], e2[3]));
        u64 sq = mul2(e2[0], e2[0]);
        sq = fma2(e2[1], e2[1], sq);
        sq = fma2(e2[2], e2[2], sq);
        sq = fma2(e2[3], e2[3], sq);
        float selo, sehi, sqlo, sqhi;
        upk(se, selo, sehi); upk(sq, sqlo, sqhi);
        float sum = selo + sehi;
        float ssq = sqlo + sqhi;

        // full-warp butterfly (5 levels)
        #pragma unroll
        for (int o = 16; o; o >>= 1) {
            sum += __shfl_xor_sync(~0u, sum, o);
            ssq += __shfl_xor_sync(~0u, ssq, o);
        }
        const float mean = sum * (1.f / H);
        const float var  = fmaf(ssq, 1.f / H, -mean * mean);
        const float A    = rsqrtf(var + 1e-5f);
        smA = fmaf(mean, A, smA);
        const u64 A2 = pk(A, A);
        #pragma unroll
        for (int p = 0; p < 4; ++p) acc2[p] = fma2(e2[p], A2, acc2[p]);
    }

    __syncthreads();                       // all warps done reading sv
    {
        const u64 nsmA = pk(-smA, -smA);
        u64* dst = (u64*)&sv[w * H + lane * 8];
        #pragma unroll
        for (int p = 0; p < 4; ++p) dst[p] = add2(acc2[p], nsmA);
    }
    __syncthreads();
    {
        float s = 0.f;
        #pragma unroll
        for (int ww = 0; ww < 8; ++ww) s += sv[ww * H + tid];
        // block covers 8 i * 16 j = 128 pairs -> 128 * beta
        g_p[bid * H + tid] = fmaf(lg[tid], s, 128.f * lb[tid]);
    }
}

// ---------------------------------------------------------------------------
// K4: s[b] = Σ 32 partials; out = ELU(s @ W_f + b_f). 4-way F-split.
// ---------------------------------------------------------------------------
__global__ __launch_bounds__(256) void k_final(
    const float* __restrict__ Wf, const float* __restrict__ bf,
    float* __restrict__ out)
{
    const int bid  = blockIdx.x;
    const int b    = bid >> 2;
    const int fq   = bid & 3;
    const int tid  = threadIdx.x;
    const int w    = tid >> 5;
    const int lane = tid & 31;
    __shared__ float ss[H];
    __shared__ float part[8][32];

    {
        float s = 0.f;
        #pragma unroll 8
        for (int ig = 0; ig < 32; ++ig) s += g_p[(b * 32 + ig) * H + tid];
        ss[tid] = s;
    }
    __syncthreads();

    const int f  = fq * 32 + lane;
    const int h0 = w * 32;
    float a0 = 0.f, a1 = 0.f, a2 = 0.f, a3 = 0.f;
    #pragma unroll
    for (int hh = 0; hh < 32; hh += 4) {
        a0 = fmaf(ss[h0 + hh + 0], Wf[(h0 + hh + 0) * F + f], a0);
        a1 = fmaf(ss[h0 + hh + 1], Wf[(h0 + hh + 1) * F + f], a1);
        a2 = fmaf(ss[h0 + hh + 2], Wf[(h0 + hh + 2) * F + f], a2);
        a3 = fmaf(ss[h0 + hh + 3], Wf[(h0 + hh + 3) * F + f], a3);
    }
    part[w][lane] = (a0 + a1) + (a2 + a3);
    __syncthreads();

    if (w == 0) {
        float o = bf[f];
        #pragma unroll
        for (int k = 0; k < 8; ++k) o += part[k][lane];
        out[b * F + f] = (o > 0.f) ? o : expm1f(o);
    }
}

// ---------------------------------------------------------------------------
extern "C" void kernel_launch(void* const* d_in, const int* in_sizes, int n_in,
                              void* d_out, int out_size)
{
    const float* x_a   = (const float*)d_in[0];
    const float* x_b   = (const float*)d_in[1];
    const float* W_a   = (const float*)d_in[2];
    const float* b_a   = (const float*)d_in[3];
    const float* W_b   = (const float*)d_in[4];
    const float* b_b   = (const float*)d_in[5];
    const float* ln0_g = (const float*)d_in[6];
    const float* ln0_b = (const float*)d_in[7];
    const float* W_g   = (const float*)d_in[8];
    const float* b_g   = (const float*)d_in[9];
    const float* lng_g = (const float*)d_in[10];
    const float* lng_b = (const float*)d_in[11];
    const float* W_f   = (const float*)d_in[12];
    const float* b_f   = (const float*)d_in[13];
    float* out = (float*)d_out;

    k_embed_ln<<<B, 256>>>(x_a, x_b, W_a, b_a, W_b, b_b, ln0_g, ln0_b);
    k_uv<<<B * NN / 16, 256>>>(W_g, b_g);

    const size_t smem = 16 * H * sizeof(float);   // 16 KB
    cudaFuncSetAttribute(k_pair, cudaFuncAttributeMaxDynamicSharedMemorySize, (int)smem);
    k_pair<<<B * 32, 256, smem>>>(lng_g, lng_b);

    k_final<<<B * 4, 256>>>(W_f, b_f, out);
}